// round 2
// baseline (speedup 1.0000x reference)
#include <cuda_runtime.h>

// Problem shape (fixed by setup_inputs)
#define N_IMG 16
#define M_PPL 30
#define K_JNT 17
#define S_RES 16
#define LS    1114112   // K*H*W = 17*256*256 (elements per image in tags)

__device__ float g_partial[N_IMG][3];

__global__ __launch_bounds__(512)
void ae_per_image(const float* __restrict__ tags,
                  const int* __restrict__ joints,      // JAX x64 disabled -> int32
                  const float* __restrict__ box_scales,
                  const float* __restrict__ scale_dist)
{
    const int n   = blockIdx.x;
    const int tid = threadIdx.x;

    __shared__ float s_mean[M_PPL][S_RES + 1];  // +1 pad: avoid bank conflicts in push phase
    __shared__ float s_pull[M_PPL];
    __shared__ float s_dscale[M_PPL];
    __shared__ int   s_valid[M_PPL];
    __shared__ float s_push;
    __shared__ int   s_nvalid;

    if (tid == 0) { s_push = 0.f; s_nvalid = 0; }
    __syncthreads();

    // ---------------- Phase 1: per-person stats (threads m*16+s, m<30, s<16) --------
    if (tid < M_PPL * S_RES) {
        const int m = tid >> 4;
        const int s = tid & 15;

        const int* jp      = joints + (n * M_PPL + m) * K_JNT * 2;
        const float* tbase = tags + (long long)n * LS;

        float g[K_JNT];
        unsigned visMask = 0u;
        float sumv = 0.f;
        int cnt = 0;

        #pragma unroll
        for (int k = 0; k < K_JNT; k++) {
            int loc = jp[2 * k];                  // broadcast across the 16-lane group
            int v   = (jp[2 * k + 1] > 0);
            float val = tbase[(long long)loc * S_RES + s];  // coalesced 64B per group
            g[k] = val;
            if (v) { sumv += val; cnt++; visMask |= (1u << k); }
        }

        const float safe_cnt = fmaxf((float)cnt, 1.f);
        const float mean = sumv / safe_cnt;
        s_mean[m][s] = mean;

        // pull: sum over visible k of (g-mean)^2, then reduce over s
        float p = 0.f;
        #pragma unroll
        for (int k = 0; k < K_JNT; k++) {
            if (visMask & (1u << k)) { float d = g[k] - mean; p += d * d; }
        }
        #pragma unroll
        for (int off = 8; off; off >>= 1) p += __shfl_xor_sync(0xffffffffu, p, off);

        // scale term
        const float bs  = box_scales[n * M_PPL + m];
        const float gap = fabsf(bs - scale_dist[s]);
        const float inv = 1.f / (gap + 1e-10f);
        const float am  = fabsf(mean);

        float n1 = inv * inv;
        float n2 = am * am;
        #pragma unroll
        for (int off = 8; off; off >>= 1) {
            n1 += __shfl_xor_sync(0xffffffffu, n1, off);
            n2 += __shfl_xor_sync(0xffffffffu, n2, off);
        }
        const float tnorm = fmaxf(sqrtf(n1), 1e-12f);
        const float pnorm = fmaxf(sqrtf(n2), 1e-12f);
        float dot = (inv / tnorm) * (am / pnorm);
        #pragma unroll
        for (int off = 8; off; off >>= 1) dot += __shfl_xor_sync(0xffffffffu, dot, off);

        if (s == 0) {
            s_pull[m]   = p / (safe_cnt * (float)S_RES);
            s_dscale[m] = 1.f - dot;
            const int valid = (cnt > 0);
            s_valid[m] = valid;
            if (valid) atomicAdd(&s_nvalid, 1);
        }
    }
    __syncthreads();

    // ---------------- Phase 2: push (pairwise over M*M) ----------------------------
    float local = 0.f;
    for (int p = tid; p < M_PPL * M_PPL; p += blockDim.x) {
        const int a = p / M_PPL;
        const int b = p % M_PPL;
        if (a != b && s_valid[a] && s_valid[b]) {
            float d = 0.f;
            #pragma unroll
            for (int s2 = 0; s2 < S_RES; s2++) {
                float t = s_mean[a][s2] - s_mean[b][s2];
                d += t * t;
            }
            local += expf(-d);
        }
    }
    #pragma unroll
    for (int off = 16; off; off >>= 1) local += __shfl_xor_sync(0xffffffffu, local, off);
    if ((tid & 31) == 0) atomicAdd(&s_push, local);
    __syncthreads();

    // ---------------- Finalize per-image -------------------------------------------
    if (tid == 0) {
        const float nv = (float)s_nvalid;
        const float safe_n = fmaxf(nv, 1.f);
        float pull_img = 0.f, scale_img = 0.f;
        #pragma unroll
        for (int m = 0; m < M_PPL; m++) {
            if (s_valid[m]) { pull_img += s_pull[m]; scale_img += s_dscale[m]; }
        }
        pull_img  /= safe_n;
        scale_img /= safe_n;
        const float push_img = (nv >= 2.f)
            ? 0.5f * s_push / fmaxf(nv * (nv - 1.f), 1.f)
            : 0.f;
        g_partial[n][0] = pull_img;
        g_partial[n][1] = push_img;
        g_partial[n][2] = scale_img;
    }
}

__global__ void ae_reduce(float* __restrict__ out)
{
    const int t = threadIdx.x;
    if (t < 3) {
        float s = 0.f;
        #pragma unroll
        for (int n = 0; n < N_IMG; n++) s += g_partial[n][t];
        out[t] = s / (float)N_IMG;   // order: pull, push, scale
    }
}

extern "C" void kernel_launch(void* const* d_in, const int* in_sizes, int n_in,
                              void* d_out, int out_size)
{
    const float* tags       = (const float*)d_in[0];
    const int*   joints     = (const int*)d_in[1];
    const float* box_scales = (const float*)d_in[2];
    const float* scale_dist = (const float*)d_in[3];
    float* out = (float*)d_out;

    ae_per_image<<<N_IMG, 512>>>(tags, joints, box_scales, scale_dist);
    ae_reduce<<<1, 32>>>(out);
}

// round 4
// speedup vs baseline: 1.0031x; 1.0031x over previous
#include <cuda_runtime.h>

// Problem shape (fixed by setup_inputs)
#define N_IMG 16
#define M_PPL 30
#define K_JNT 17
#define S_RES 16
#define LS    1114112   // K*H*W = 17*256*256 (elements per image in tags)

__device__ float g_partial[N_IMG][3];
__device__ unsigned int g_counter = 0;

__global__ __launch_bounds__(480)
void ae_fused(const float* __restrict__ tags,
              const int* __restrict__ joints,      // JAX x64 disabled -> int32
              const float* __restrict__ box_scales,
              const float* __restrict__ scale_dist,
              float* __restrict__ out)
{
    const int n   = blockIdx.x;
    const int tid = threadIdx.x;

    __shared__ float s_mean[M_PPL][S_RES + 1];  // +1 pad: avoid bank conflicts in push phase
    __shared__ float s_pull[M_PPL];
    __shared__ float s_dscale[M_PPL];
    __shared__ int   s_valid[M_PPL];
    __shared__ float s_push;
    __shared__ int   s_nvalid;
    __shared__ unsigned s_ticket;

    if (tid == 0) { s_push = 0.f; s_nvalid = 0; }
    __syncthreads();

    // ---------------- Phase 1: per-person stats (threads m*16+s, m<30, s<16) --------
    {
        const int m = tid >> 4;
        const int s = tid & 15;

        const int* jp      = joints + (n * M_PPL + m) * K_JNT * 2;
        const float* tbase = tags + (long long)n * LS;

        float g[K_JNT];
        unsigned visMask = 0u;
        float sumv = 0.f;
        int cnt = 0;

        #pragma unroll
        for (int k = 0; k < K_JNT; k++) {
            int loc = jp[2 * k];                  // broadcast across the 16-lane group
            int v   = (jp[2 * k + 1] > 0);
            float val = tbase[(long long)loc * S_RES + s];  // coalesced 64B per group
            g[k] = val;
            if (v) { sumv += val; cnt++; visMask |= (1u << k); }
        }

        const float safe_cnt = fmaxf((float)cnt, 1.f);
        const float mean = sumv / safe_cnt;
        s_mean[m][s] = mean;

        // pull: sum over visible k of (g-mean)^2, then reduce over s (16-lane half-warp)
        float p = 0.f;
        #pragma unroll
        for (int k = 0; k < K_JNT; k++) {
            if (visMask & (1u << k)) { float d = g[k] - mean; p += d * d; }
        }
        #pragma unroll
        for (int off = 8; off; off >>= 1) p += __shfl_xor_sync(0xffffffffu, p, off);

        // scale term
        const float bs  = box_scales[n * M_PPL + m];
        const float gap = fabsf(bs - scale_dist[s]);
        const float inv = 1.f / (gap + 1e-10f);
        const float am  = fabsf(mean);

        float n1 = inv * inv;
        float n2 = am * am;
        #pragma unroll
        for (int off = 8; off; off >>= 1) {
            n1 += __shfl_xor_sync(0xffffffffu, n1, off);
            n2 += __shfl_xor_sync(0xffffffffu, n2, off);
        }
        const float tnorm = fmaxf(sqrtf(n1), 1e-12f);
        const float pnorm = fmaxf(sqrtf(n2), 1e-12f);
        float dot = (inv / tnorm) * (am / pnorm);
        #pragma unroll
        for (int off = 8; off; off >>= 1) dot += __shfl_xor_sync(0xffffffffu, dot, off);

        if (s == 0) {
            s_pull[m]   = p / (safe_cnt * (float)S_RES);
            s_dscale[m] = 1.f - dot;
            const int valid = (cnt > 0);
            s_valid[m] = valid;
            if (valid) atomicAdd(&s_nvalid, 1);
        }
    }
    __syncthreads();

    // ---------------- Phase 2: push (pairwise over M*M, 900 pairs / 480 thr) -------
    float local = 0.f;
    #pragma unroll
    for (int it = 0; it < 2; it++) {
        const int p = tid + it * 480;
        if (p < M_PPL * M_PPL) {
            const int a = p / M_PPL;
            const int b = p % M_PPL;
            if (a != b && s_valid[a] && s_valid[b]) {
                float d = 0.f;
                #pragma unroll
                for (int s2 = 0; s2 < S_RES; s2++) {
                    float t = s_mean[a][s2] - s_mean[b][s2];
                    d += t * t;
                }
                local += expf(-d);
            }
        }
    }
    #pragma unroll
    for (int off = 16; off; off >>= 1) local += __shfl_xor_sync(0xffffffffu, local, off);
    if ((tid & 31) == 0) atomicAdd(&s_push, local);
    __syncthreads();

    // ---------------- Finalize per-image -------------------------------------------
    if (tid == 0) {
        const float nv = (float)s_nvalid;
        const float safe_n = fmaxf(nv, 1.f);
        float pull_img = 0.f, scale_img = 0.f;
        #pragma unroll
        for (int m = 0; m < M_PPL; m++) {
            if (s_valid[m]) { pull_img += s_pull[m]; scale_img += s_dscale[m]; }
        }
        pull_img  /= safe_n;
        scale_img /= safe_n;
        const float push_img = (nv >= 2.f)
            ? 0.5f * s_push / fmaxf(nv * (nv - 1.f), 1.f)
            : 0.f;
        g_partial[n][0] = pull_img;
        g_partial[n][1] = push_img;
        g_partial[n][2] = scale_img;

        __threadfence();
        s_ticket = atomicAdd(&g_counter, 1u);
    }
    __syncthreads();

    // ---------------- Last block: global reduce + counter reset ---------------------
    if (s_ticket == N_IMG - 1) {
        if (tid < 3) {
            float s = 0.f;
            #pragma unroll
            for (int i = 0; i < N_IMG; i++) s += g_partial[i][tid];
            out[tid] = s / (float)N_IMG;   // order: pull, push, scale
        }
        __threadfence();
        if (tid == 0) g_counter = 0;       // reset for next graph replay
    }
}

extern "C" void kernel_launch(void* const* d_in, const int* in_sizes, int n_in,
                              void* d_out, int out_size)
{
    const float* tags       = (const float*)d_in[0];
    const int*   joints     = (const int*)d_in[1];
    const float* box_scales = (const float*)d_in[2];
    const float* scale_dist = (const float*)d_in[3];
    float* out = (float*)d_out;

    ae_fused<<<N_IMG, 480>>>(tags, joints, box_scales, scale_dist, out);
}